// round 9
// baseline (speedup 1.0000x reference)
#include <cuda_runtime.h>

// Depthwise 3x3 conv, stride 1, VALID, fp32.
// x: (16, 64, 512, 512), weight: (64, 3, 3), out: (16, 64, 510, 510)

#define CCH    64
#define HH     512
#define WW     512
#define OHT    510
#define OWD    510
#define ROWS   30     // output rows per CTA (17 * 30 = 510)
#define NTILES 17

__global__ __launch_bounds__(128, 12)   // 12 CTAs/SM, 40 regs — measured pareto point
void dwconv3x3_kernel(const float* __restrict__ x,
                      const float* __restrict__ wgt,
                      float* __restrict__ out)
{
    const int tile = blockIdx.x;          // 0..16 (fast-varying: same-plane tiles co-resident)
    const int nc   = blockIdx.y;          // n*64 + c
    const int c    = nc & (CCH - 1);

    const float* xp = x   + (size_t)nc * HH * WW;
    float*       op = out + (size_t)nc * OHT * OWD;

    float wt[9];
#pragma unroll
    for (int i = 0; i < 9; i++) wt[i] = __ldg(wgt + c * 9 + i);

    const int  tid   = threadIdx.x;       // 0..127
    const int  x0    = tid * 4;           // output cols x0..x0+3
    const bool hi_ok = (tid < 127);       // tid 127: cols 510/511 invalid, halo OOB
    const int  y0    = tile * ROWS;

    // Sliding window: rows y..y+2 resident (float4 body + float2 halo each).
    // Input lines are single-use at L2 (measured) -> stream them (__ldcs).
    float4 a0, a1, a2;
    float2 b0, b1, b2;
    {
        const float* r = xp + (size_t)y0 * WW + x0;
        a0 = __ldcs((const float4*)(r));
        a1 = __ldcs((const float4*)(r + WW));
        a2 = __ldcs((const float4*)(r + 2 * WW));
        if (hi_ok) {
            b0 = __ldcs((const float2*)(r + 4));
            b1 = __ldcs((const float2*)(r + WW + 4));
            b2 = __ldcs((const float2*)(r + 2 * WW + 4));
        } else {
            b0 = b1 = b2 = make_float2(0.f, 0.f);
        }
    }

    // Prefetch pointer (row y0+3), output pointer — both incremented, no per-iter IMAD.
    const float* rp      = xp + (size_t)(y0 + 3) * WW + x0;
    const float* rp_last = xp + (size_t)(HH - 1) * WW + x0;
    float*       orow    = op + (size_t)y0 * OWD + x0;

#pragma unroll 1
    for (int yy = 0; yy < ROWS; yy++) {
        // ---- prefetch next row (consumed NEXT iteration; clamp at image edge) ----
        const float* rr = (rp > rp_last) ? rp_last : rp;
        float4 pa = __ldcs((const float4*)rr);
        float2 pb = hi_ok ? __ldcs((const float2*)(rr + 4)) : make_float2(0.f, 0.f);
        rp += WW;

        // ---- compute output row y0+yy from resident rows ----
        const float v0[6] = {a0.x, a0.y, a0.z, a0.w, b0.x, b0.y};
        const float v1[6] = {a1.x, a1.y, a1.z, a1.w, b1.x, b1.y};
        const float v2[6] = {a2.x, a2.y, a2.z, a2.w, b2.x, b2.y};

        float acc[4];
#pragma unroll
        for (int j = 0; j < 4; j++) {
            float s = v0[j] * wt[0];
            s = fmaf(v0[j + 1], wt[1], s);
            s = fmaf(v0[j + 2], wt[2], s);
            s = fmaf(v1[j],     wt[3], s);
            s = fmaf(v1[j + 1], wt[4], s);
            s = fmaf(v1[j + 2], wt[5], s);
            s = fmaf(v2[j],     wt[6], s);
            s = fmaf(v2[j + 1], wt[7], s);
            s = fmaf(v2[j + 2], wt[8], s);
            acc[j] = s;
        }

        // ---- stores: rows always 8B-aligned (2040B stride) -> STG.64 streaming ----
        __stcs((float2*)orow, make_float2(acc[0], acc[1]));
        if (hi_ok)                              // tid 127: cols 510/511 are OOB
            __stcs((float2*)(orow + 2), make_float2(acc[2], acc[3]));
        orow += OWD;

        // ---- rotate window ----
        a0 = a1; b0 = b1;
        a1 = a2; b1 = b2;
        a2 = pa; b2 = pb;
    }
}

extern "C" void kernel_launch(void* const* d_in, const int* in_sizes, int n_in,
                              void* d_out, int out_size)
{
    const float* x   = (const float*)d_in[0];
    const float* wgt = (const float*)d_in[1];
    float*       out = (float*)d_out;

    dim3 grid(NTILES, 16 * CCH);   // 17 row tiles (fast) x 1024 (n,c) planes
    dwconv3x3_kernel<<<grid, 128>>>(x, wgt, out);
}

// round 10
// speedup vs baseline: 1.0628x; 1.0628x over previous
#include <cuda_runtime.h>

// Depthwise 3x3 conv, stride 1, VALID, fp32.
// x: (16, 64, 512, 512), weight: (64, 3, 3), out: (16, 64, 510, 510)

#define CCH    64
#define HH     512
#define WW     512
#define OHT    510
#define OWD    510
#define ROWS   30     // output rows per CTA (17 * 30 = 510)
#define NTILES 17

__global__ __launch_bounds__(128, 12)   // 12 CTAs/SM, 40 regs — measured pareto point
void dwconv3x3_kernel(const float* __restrict__ x,
                      const float* __restrict__ wgt,
                      float* __restrict__ out)
{
    const int tile = blockIdx.x;          // 0..16 (fast-varying: same-plane tiles co-resident)
    const int nc   = blockIdx.y;          // n*64 + c
    const int c    = nc & (CCH - 1);

    const float* xp = x   + (size_t)nc * HH * WW;
    float*       op = out + (size_t)nc * OHT * OWD;

    float wt[9];
#pragma unroll
    for (int i = 0; i < 9; i++) wt[i] = __ldg(wgt + c * 9 + i);

    const int  tid   = threadIdx.x;       // 0..127
    const int  x0    = tid * 4;           // output cols x0..x0+3
    const bool hi_ok = (tid < 127);       // tid 127: cols 510/511 invalid, halo OOB
    const int  y0    = tile * ROWS;

    // Sliding window: rows y..y+2 resident (float4 body + float2 halo each).
    // DEFAULT-cached loads: the float2 halo hits L1 via the neighbor thread's
    // float4 line — evict-first (.cs) here was measured to cost +60us (R7).
    float4 a0, a1, a2;
    float2 b0, b1, b2;
    {
        const float* r = xp + (size_t)y0 * WW + x0;
        a0 = *(const float4*)(r);
        a1 = *(const float4*)(r + WW);
        a2 = *(const float4*)(r + 2 * WW);
        if (hi_ok) {
            b0 = *(const float2*)(r + 4);
            b1 = *(const float2*)(r + WW + 4);
            b2 = *(const float2*)(r + 2 * WW + 4);
        } else {
            b0 = b1 = b2 = make_float2(0.f, 0.f);
        }
    }

    // Prefetch pointer (row y0+3) and output pointer, both strength-reduced.
    const float* rp      = xp + (size_t)(y0 + 3) * WW + x0;
    const float* rp_last = xp + (size_t)(HH - 1) * WW + x0;
    float*       orow    = op + (size_t)y0 * OWD + x0;

#pragma unroll 1
    for (int yy = 0; yy < ROWS; yy++) {
        // ---- prefetch next row (consumed NEXT iteration; clamp at image edge) ----
        const float* rr = (rp > rp_last) ? rp_last : rp;
        float4 pa = *(const float4*)rr;
        float2 pb = hi_ok ? *(const float2*)(rr + 4) : make_float2(0.f, 0.f);
        rp += WW;

        // ---- compute output row y0+yy from resident rows ----
        const float v0[6] = {a0.x, a0.y, a0.z, a0.w, b0.x, b0.y};
        const float v1[6] = {a1.x, a1.y, a1.z, a1.w, b1.x, b1.y};
        const float v2[6] = {a2.x, a2.y, a2.z, a2.w, b2.x, b2.y};

        float acc[4];
#pragma unroll
        for (int j = 0; j < 4; j++) {
            float s = v0[j] * wt[0];
            s = fmaf(v0[j + 1], wt[1], s);
            s = fmaf(v0[j + 2], wt[2], s);
            s = fmaf(v1[j],     wt[3], s);
            s = fmaf(v1[j + 1], wt[4], s);
            s = fmaf(v1[j + 2], wt[5], s);
            s = fmaf(v2[j],     wt[6], s);
            s = fmaf(v2[j + 1], wt[7], s);
            s = fmaf(v2[j + 2], wt[8], s);
            acc[j] = s;
        }

        // ---- stores: rows always 8B-aligned (2040B stride) -> STG.64 streaming ----
        __stcs((float2*)orow, make_float2(acc[0], acc[1]));
        if (hi_ok)                              // tid 127: cols 510/511 are OOB
            __stcs((float2*)(orow + 2), make_float2(acc[2], acc[3]));
        orow += OWD;

        // ---- rotate window ----
        a0 = a1; b0 = b1;
        a1 = a2; b1 = b2;
        a2 = pa; b2 = pb;
    }
}

extern "C" void kernel_launch(void* const* d_in, const int* in_sizes, int n_in,
                              void* d_out, int out_size)
{
    const float* x   = (const float*)d_in[0];
    const float* wgt = (const float*)d_in[1];
    float*       out = (float*)d_out;

    dim3 grid(NTILES, 16 * CCH);   // 17 row tiles (fast) x 1024 (n,c) planes
    dwconv3x3_kernel<<<grid, 128>>>(x, wgt, out);
}

// round 11
// speedup vs baseline: 1.1896x; 1.1193x over previous
#include <cuda_runtime.h>

// Depthwise 3x3 conv, stride 1, VALID, fp32.
// x: (16, 64, 512, 512), weight: (64, 3, 3), out: (16, 64, 510, 510)

#define CCH    64
#define HH     512
#define WW     512
#define OHT    510
#define OWD    510
#define ROWS   30     // output rows per CTA (17 * 30 = 510)
#define NTILES 17

__global__ __launch_bounds__(128, 12)
void dwconv3x3_kernel(const float* __restrict__ x,
                      const float* __restrict__ wgt,
                      float* __restrict__ out)
{
    const int tile = blockIdx.x;          // 0..16  (fastest-varying -> tiles of one
    const int nc   = blockIdx.y;          //          plane run concurrently, halo hits L2)
    const int c    = nc & (CCH - 1);

    const float* xp = x   + (size_t)nc * HH * WW;
    float*       op = out + (size_t)nc * OHT * OWD;

    float wt[9];
#pragma unroll
    for (int i = 0; i < 9; i++) wt[i] = __ldg(wgt + c * 9 + i);

    const int  tid   = threadIdx.x;       // 0..127
    const int  x0    = tid * 4;           // output cols x0..x0+3
    const bool hi_ok = (tid < 127);       // tid 127: cols 510/511 invalid, halo OOB
    const int  y0    = tile * ROWS;

    // Sliding window: rows y..y+2 resident (float4 body + float2 halo each).
    float4 a0, a1, a2;
    float2 b0, b1, b2;
    {
        const float* r = xp + (size_t)y0 * WW + x0;
        a0 = *(const float4*)(r);
        a1 = *(const float4*)(r + WW);
        a2 = *(const float4*)(r + 2 * WW);
        if (hi_ok) {
            b0 = *(const float2*)(r + 4);
            b1 = *(const float2*)(r + WW + 4);
            b2 = *(const float2*)(r + 2 * WW + 4);
        } else {
            b0 = b1 = b2 = make_float2(0.f, 0.f);
        }
    }

    // Pointer for prefetch row y0+3, advanced by one row each iteration.
    // NOTE: no unroll pragma on the loop below — compile-time trip count lets
    // nvcc unroll with register rotation (batched LDGs, no window-copy MOVs).
    // Pinning unroll to 1 was measured at +38us (R9).
    const float* rp      = xp + (size_t)(y0 + 3) * WW + x0;
    const float* rp_last = xp + (size_t)(HH - 1) * WW + x0;

    for (int yy = 0; yy < ROWS; yy++) {
        // ---- prefetch next row (consumed NEXT iteration; clamp at image edge) ----
        const float* rr = (rp > rp_last) ? rp_last : rp;
        float4 pa = *(const float4*)rr;
        float2 pb = hi_ok ? *(const float2*)(rr + 4) : make_float2(0.f, 0.f);
        rp += WW;

        // ---- compute output row y0+yy from resident rows ----
        const float v0[6] = {a0.x, a0.y, a0.z, a0.w, b0.x, b0.y};
        const float v1[6] = {a1.x, a1.y, a1.z, a1.w, b1.x, b1.y};
        const float v2[6] = {a2.x, a2.y, a2.z, a2.w, b2.x, b2.y};

        float acc[4];
#pragma unroll
        for (int j = 0; j < 4; j++) {
            float s = v0[j] * wt[0];
            s = fmaf(v0[j + 1], wt[1], s);
            s = fmaf(v0[j + 2], wt[2], s);
            s = fmaf(v1[j],     wt[3], s);
            s = fmaf(v1[j + 1], wt[4], s);
            s = fmaf(v1[j + 2], wt[5], s);
            s = fmaf(v2[j],     wt[6], s);
            s = fmaf(v2[j + 1], wt[7], s);
            s = fmaf(v2[j + 2], wt[8], s);
            acc[j] = s;
        }

        // ---- stores: rows always 8B-aligned (2040B stride) -> STG.64 streaming ----
        float* orow = op + (size_t)(y0 + yy) * OWD + x0;
        __stcs((float2*)orow, make_float2(acc[0], acc[1]));
        if (hi_ok)                              // tid 127: cols 510/511 are OOB
            __stcs((float2*)(orow + 2), make_float2(acc[2], acc[3]));

        // ---- rotate window ----
        a0 = a1; b0 = b1;
        a1 = a2; b1 = b2;
        a2 = pa; b2 = pb;
    }
}

extern "C" void kernel_launch(void* const* d_in, const int* in_sizes, int n_in,
                              void* d_out, int out_size)
{
    const float* x   = (const float*)d_in[0];
    const float* wgt = (const float*)d_in[1];
    float*       out = (float*)d_out;

    dim3 grid(NTILES, 16 * CCH);   // 17 row tiles (fast) x 1024 (n,c) planes
    dwconv3x3_kernel<<<grid, 128>>>(x, wgt, out);
}

// round 12
// speedup vs baseline: 1.2342x; 1.0375x over previous
#include <cuda_runtime.h>

// Depthwise 3x3 conv, stride 1, VALID, fp32.
// x: (16, 64, 512, 512), weight: (64, 3, 3), out: (16, 64, 510, 510)

#define CCH    64
#define HH     512
#define WW     512
#define OHT    510
#define OWD    510
#define ROWS   30     // output rows per CTA (17 * 30 = 510)
#define NTILES 17

__global__ __launch_bounds__(128, 12)
void dwconv3x3_kernel(const float* __restrict__ x,
                      const float* __restrict__ wgt,
                      float* __restrict__ out)
{
    const int tile = blockIdx.x;          // 0..16 (fast-varying: same-plane tiles co-wave)
    const int nc   = blockIdx.y;          // n*64 + c
    const int c    = nc & (CCH - 1);

    const float* xp = x   + (size_t)nc * HH * WW;
    float*       op = out + (size_t)nc * OHT * OWD;

    float wt[9];
#pragma unroll
    for (int i = 0; i < 9; i++) wt[i] = __ldg(wgt + c * 9 + i);

    const int  tid   = threadIdx.x;       // 0..127
    const int  x0    = tid * 4;           // output cols x0..x0+3
    const bool hi_ok = (tid < 127);       // tid 127: cols 510/511 invalid, halo OOB
    const int  y0    = tile * ROWS;

    if (!(tile & 1)) {
        // ================= even tiles: sweep top -> bottom =================
        float4 a0, a1, a2;
        float2 b0, b1, b2;
        {
            const float* r = xp + (size_t)y0 * WW + x0;
            a0 = *(const float4*)(r);
            a1 = *(const float4*)(r + WW);
            a2 = *(const float4*)(r + 2 * WW);
            if (hi_ok) {
                b0 = *(const float2*)(r + 4);
                b1 = *(const float2*)(r + WW + 4);
                b2 = *(const float2*)(r + 2 * WW + 4);
            } else {
                b0 = b1 = b2 = make_float2(0.f, 0.f);
            }
        }

        const float* rp      = xp + (size_t)(y0 + 3) * WW + x0;
        const float* rp_last = xp + (size_t)(HH - 1) * WW + x0;

        for (int yy = 0; yy < ROWS; yy++) {
            const float* rr = (rp > rp_last) ? rp_last : rp;   // clamp (tile 16 edge)
            float4 pa = *(const float4*)rr;
            float2 pb = hi_ok ? *(const float2*)(rr + 4) : make_float2(0.f, 0.f);
            rp += WW;

            const float v0[6] = {a0.x, a0.y, a0.z, a0.w, b0.x, b0.y};
            const float v1[6] = {a1.x, a1.y, a1.z, a1.w, b1.x, b1.y};
            const float v2[6] = {a2.x, a2.y, a2.z, a2.w, b2.x, b2.y};

            float acc[4];
#pragma unroll
            for (int j = 0; j < 4; j++) {
                float s = v0[j] * wt[0];
                s = fmaf(v0[j + 1], wt[1], s);
                s = fmaf(v0[j + 2], wt[2], s);
                s = fmaf(v1[j],     wt[3], s);
                s = fmaf(v1[j + 1], wt[4], s);
                s = fmaf(v1[j + 2], wt[5], s);
                s = fmaf(v2[j],     wt[6], s);
                s = fmaf(v2[j + 1], wt[7], s);
                s = fmaf(v2[j + 2], wt[8], s);
                acc[j] = s;
            }

            float* orow = op + (size_t)(y0 + yy) * OWD + x0;
            __stcs((float2*)orow, make_float2(acc[0], acc[1]));
            if (hi_ok)
                __stcs((float2*)(orow + 2), make_float2(acc[2], acc[3]));

            a0 = a1; b0 = b1;
            a1 = a2; b1 = b2;
            a2 = pa; b2 = pb;
        }
    } else {
        // ================= odd tiles: sweep bottom -> top ==================
        // Serpentine: boundary rows shared with neighbor tiles are then read
        // in the same phase of execution -> second read hits L2, not DRAM.
        float4 a0, a1, a2;
        float2 b0, b1, b2;
        {
            const float* r = xp + (size_t)(y0 + ROWS - 1) * WW + x0;   // rows y0+29..y0+31
            a0 = *(const float4*)(r);
            a1 = *(const float4*)(r + WW);
            a2 = *(const float4*)(r + 2 * WW);
            if (hi_ok) {
                b0 = *(const float2*)(r + 4);
                b1 = *(const float2*)(r + WW + 4);
                b2 = *(const float2*)(r + 2 * WW + 4);
            } else {
                b0 = b1 = b2 = make_float2(0.f, 0.f);
            }
        }

        // Prefetch row y0+yy-1 each iteration; odd tiles have y0 >= 30 so the
        // final prefetch (row y0-1 >= 29) is always in-bounds: no clamp needed.
        const float* rp = xp + (size_t)(y0 + ROWS - 2) * WW + x0;

        for (int yy = ROWS - 1; yy >= 0; yy--) {
            float4 pa = *(const float4*)rp;
            float2 pb = hi_ok ? *(const float2*)(rp + 4) : make_float2(0.f, 0.f);
            rp -= WW;

            const float v0[6] = {a0.x, a0.y, a0.z, a0.w, b0.x, b0.y};
            const float v1[6] = {a1.x, a1.y, a1.z, a1.w, b1.x, b1.y};
            const float v2[6] = {a2.x, a2.y, a2.z, a2.w, b2.x, b2.y};

            float acc[4];
#pragma unroll
            for (int j = 0; j < 4; j++) {
                float s = v0[j] * wt[0];
                s = fmaf(v0[j + 1], wt[1], s);
                s = fmaf(v0[j + 2], wt[2], s);
                s = fmaf(v1[j],     wt[3], s);
                s = fmaf(v1[j + 1], wt[4], s);
                s = fmaf(v1[j + 2], wt[5], s);
                s = fmaf(v2[j],     wt[6], s);
                s = fmaf(v2[j + 1], wt[7], s);
                s = fmaf(v2[j + 2], wt[8], s);
                acc[j] = s;
            }

            float* orow = op + (size_t)(y0 + yy) * OWD + x0;
            __stcs((float2*)orow, make_float2(acc[0], acc[1]));
            if (hi_ok)
                __stcs((float2*)(orow + 2), make_float2(acc[2], acc[3]));

            // rotate window upward
            a2 = a1; b2 = b1;
            a1 = a0; b1 = b0;
            a0 = pa; b0 = pb;
        }
    }
}

extern "C" void kernel_launch(void* const* d_in, const int* in_sizes, int n_in,
                              void* d_out, int out_size)
{
    const float* x   = (const float*)d_in[0];
    const float* wgt = (const float*)d_in[1];
    float*       out = (float*)d_out;

    dim3 grid(NTILES, 16 * CCH);   // 17 row tiles (fast) x 1024 (n,c) planes
    dwconv3x3_kernel<<<grid, 128>>>(x, wgt, out);
}